// round 6
// baseline (speedup 1.0000x reference)
#include <cuda_runtime.h>
#include <cuda_fp16.h>
#include <mma.h>
#include <math.h>

using namespace nvcuda;

#define NN 100000
#define EE 1000000
#define RR 3
#define IN_DIM 128
#define OUT_DIM 64

static constexpr int N3 = RR * NN;
static constexpr int E3 = RR * EE;
static constexpr int NB_SCAN = (N3 + 255) / 256;

// ---------------- scratch ----------------------------------------------------
__device__ int     g_cnt[N3];
__device__ int     g_rowptr[N3 + 1];
__device__ int     g_col[E3];
__device__ int     g_bsum[2048];
__device__ __half2 g_h2[(size_t)N3 * (OUT_DIM / 2)];
__device__ float   g_alsrc[N3];
__device__ float   g_aldst[N3];
__device__ float   g_hmid[(size_t)NN * OUT_DIM];

// ---------------- CSR build --------------------------------------------------
__global__ void k_hist(const int* __restrict__ e0, const int* __restrict__ e1,
                       const int* __restrict__ e2) {
    int i = blockIdx.x * blockDim.x + threadIdx.x;
    if (i >= E3) return;
    int r = i / EE, e = i - r * EE;
    const int* ei = (r == 0) ? e0 : (r == 1) ? e1 : e2;
    int dst = ei[EE + e];
    atomicAdd(&g_cnt[r * NN + dst], 1);
}

__global__ void k_scan_bsum() {
    __shared__ int sh[256];
    int i = blockIdx.x * 256 + threadIdx.x;
    sh[threadIdx.x] = (i < N3) ? g_cnt[i] : 0;
    __syncthreads();
    for (int o = 128; o > 0; o >>= 1) {
        if (threadIdx.x < o) sh[threadIdx.x] += sh[threadIdx.x + o];
        __syncthreads();
    }
    if (threadIdx.x == 0) g_bsum[blockIdx.x] = sh[0];
}

__global__ void k_scan_off_par() {
    __shared__ int sh[1024];
    int t = threadIdx.x;
    int i0 = 2 * t, i1 = 2 * t + 1;
    int a = (i0 < NB_SCAN) ? g_bsum[i0] : 0;
    int b = (i1 < NB_SCAN) ? g_bsum[i1] : 0;
    int pair = a + b;
    sh[t] = pair;
    __syncthreads();
    for (int o = 1; o < 1024; o <<= 1) {
        int add = (t >= o) ? sh[t - o] : 0;
        __syncthreads();
        sh[t] += add;
        __syncthreads();
    }
    int excl = sh[t] - pair;
    if (i0 < NB_SCAN) g_bsum[i0] = excl;
    if (i1 < NB_SCAN) g_bsum[i1] = excl + a;
}

__global__ void k_scan_final() {
    __shared__ int sh[256];
    int tid = threadIdx.x;
    int i = blockIdx.x * 256 + tid;
    int v = (i < N3) ? g_cnt[i] : 0;
    sh[tid] = v;
    __syncthreads();
    for (int o = 1; o < 256; o <<= 1) {
        int add = (tid >= o) ? sh[tid - o] : 0;
        __syncthreads();
        sh[tid] += add;
        __syncthreads();
    }
    int excl = sh[tid] - v + g_bsum[blockIdx.x];
    if (i < N3) { g_rowptr[i] = excl; g_cnt[i] = excl; }
    if (i == 0) g_rowptr[N3] = E3;
}

__global__ void k_scatter(const int* __restrict__ e0, const int* __restrict__ e1,
                          const int* __restrict__ e2) {
    int i = blockIdx.x * blockDim.x + threadIdx.x;
    if (i >= E3) return;
    int r = i / EE, e = i - r * EE;
    const int* ei = (r == 0) ? e0 : (r == 1) ? e1 : e2;
    int src = ei[e];
    int dst = ei[EE + e];
    int pos = atomicAdd(&g_cnt[r * NN + dst], 1);
    g_col[pos] = src;
}

// ---------------- tensor-core GEMM (tf32): H[r] = X @ W[r], fused logits -----
template <int K>
__global__ __launch_bounds__(256) void k_gemm_tc(
        const float* __restrict__ X, const float* __restrict__ W,
        const float* __restrict__ asrc, const float* __restrict__ adst) {
    constexpr int XLD = 20;
    constexpr int OLD = 68;
    constexpr int BUF = ((K * 64 + 128 * XLD) > (128 * OLD)) ? (K * 64 + 128 * XLD)
                                                             : (128 * OLD);
    __shared__ float buf[BUF];
    float* sW = buf;
    float* sX = buf + K * 64;
    float* sO = buf;

    const int r = blockIdx.z;
    const int row0 = blockIdx.x * 128;
    const int t = threadIdx.x;
    const int w = t >> 5;

    {
        const float4* Wr4 = (const float4*)(W + (size_t)r * K * OUT_DIM);
        for (int i = t; i < K * 16; i += 256)
            *(float4*)&sW[i * 4] = Wr4[i];
    }

    wmma::fragment<wmma::accumulator, 16, 16, 8, float> acc[4];
#pragma unroll
    for (int ct = 0; ct < 4; ct++) wmma::fill_fragment(acc[ct], 0.f);

    for (int kk = 0; kk < K; kk += 16) {
#pragma unroll
        for (int p = 0; p < 2; p++) {
            int idx = t + p * 256;
            int row = idx >> 2, c4 = (idx & 3) * 4;
            int grow = row0 + row;
            float4 v = make_float4(0.f, 0.f, 0.f, 0.f);
            if (grow < NN) v = *(const float4*)(X + (size_t)grow * K + kk + c4);
            sX[row * XLD + c4 + 0] = v.x; sX[row * XLD + c4 + 1] = v.y;
            sX[row * XLD + c4 + 2] = v.z; sX[row * XLD + c4 + 3] = v.w;
        }
        __syncthreads();
#pragma unroll
        for (int kt = 0; kt < 2; kt++) {
            wmma::fragment<wmma::matrix_a, 16, 16, 8, wmma::precision::tf32, wmma::row_major> af;
            wmma::load_matrix_sync(af, &sX[(w * 16) * XLD + kt * 8], XLD);
#pragma unroll
            for (int i = 0; i < af.num_elements; i++)
                af.x[i] = wmma::__float_to_tf32(af.x[i]);
#pragma unroll
            for (int ct = 0; ct < 4; ct++) {
                wmma::fragment<wmma::matrix_b, 16, 16, 8, wmma::precision::tf32, wmma::row_major> bf;
                wmma::load_matrix_sync(bf, &sW[(kk + kt * 8) * 64 + ct * 16], 64);
#pragma unroll
                for (int i = 0; i < bf.num_elements; i++)
                    bf.x[i] = wmma::__float_to_tf32(bf.x[i]);
                wmma::mma_sync(acc[ct], af, bf, acc[ct]);
            }
        }
        __syncthreads();
    }

#pragma unroll
    for (int ct = 0; ct < 4; ct++)
        wmma::store_matrix_sync(&sO[(w * 16) * OLD + ct * 16], acc[ct], OLD, wmma::mem_row_major);
    __syncthreads();

    {
        int row = t >> 1, half = t & 1;
        int grow = row0 + row;
        float s = 0.f, d = 0.f;
        __half2 hv[16];
        const float* orow = &sO[row * OLD + half * 32];
        const float* av = asrc + r * OUT_DIM + half * 32;
        const float* dv = adst + r * OUT_DIM + half * 32;
#pragma unroll
        for (int j = 0; j < 16; j++) {
            float v0 = orow[2 * j], v1 = orow[2 * j + 1];
            hv[j] = __float22half2_rn(make_float2(v0, v1));
            s = fmaf(v0, __ldg(&av[2 * j]), s);
            s = fmaf(v1, __ldg(&av[2 * j + 1]), s);
            d = fmaf(v0, __ldg(&dv[2 * j]), d);
            d = fmaf(v1, __ldg(&dv[2 * j + 1]), d);
        }
        float so = __shfl_xor_sync(0xffffffffu, s, 1);
        float dof = __shfl_xor_sync(0xffffffffu, d, 1);
        s += so; d += dof;
        if (grow < NN) {
            float4* dstp = (float4*)(g_h2 + (size_t)(r * NN + grow) * 32 + half * 16);
            const float4* srcp = (const float4*)hv;
#pragma unroll
            for (int q = 0; q < 4; q++) dstp[q] = srcp[q];
            if (half == 0) {
                g_alsrc[r * NN + grow] = s;
                g_aldst[r * NN + grow] = d;
            }
        }
    }
}

// ---------------- aggregation (MLP-restructured) -----------------------------
// Lanes cooperatively load 32 edge indices + compute 32 weights in parallel,
// then shuffle-broadcast (src, w) while issuing independent h2 row gathers.
template <int LAYER>
__global__ void k_agg(const float* __restrict__ bias, float2* __restrict__ out) {
    int d = (blockIdx.x * blockDim.x + threadIdx.x) >> 5;
    int lane = threadIdx.x & 31;
    if (d >= NN) return;
    float t0 = 0.f, t1 = 0.f;
#pragma unroll
    for (int r = 0; r < RR; r++) {
        int idx = r * NN + d;
        int s = g_rowptr[idx], e = g_rowptr[idx + 1];
        float ad = g_aldst[idx];
        float acc0 = 0.f, acc1 = 0.f, denl = 0.f;
        const __half2* hbase = g_h2 + (size_t)r * NN * (OUT_DIM / 2);
        const float* albase = g_alsrc + r * NN;
        for (int chunk = s; chunk < e; chunk += 32) {
            int m = e - chunk; if (m > 32) m = 32;
            int srcL = 0; float wL = 0.f;
            if (lane < m) {
                srcL = g_col[chunk + lane];                 // coalesced
                float al = albase[srcL] + ad;               // parallel gather
                float lr = al > 0.f ? al : 0.2f * al;
                wL = __expf(lr);                            // parallel MUFU
            }
            denl += wL;
            // broadcast loop: one independent 128B load per edge
            int k2 = 0;
            for (; k2 + 4 <= m; k2 += 4) {
#pragma unroll
                for (int q = 0; q < 4; q++) {
                    int src = __shfl_sync(0xffffffffu, srcL, k2 + q);
                    float w = __shfl_sync(0xffffffffu, wL, k2 + q);
                    float2 hv = __half22float2(hbase[(size_t)src * (OUT_DIM / 2) + lane]);
                    acc0 = fmaf(w, hv.x, acc0);
                    acc1 = fmaf(w, hv.y, acc1);
                }
            }
            for (; k2 < m; k2++) {
                int src = __shfl_sync(0xffffffffu, srcL, k2);
                float w = __shfl_sync(0xffffffffu, wL, k2);
                float2 hv = __half22float2(hbase[(size_t)src * (OUT_DIM / 2) + lane]);
                acc0 = fmaf(w, hv.x, acc0);
                acc1 = fmaf(w, hv.y, acc1);
            }
        }
        // reduce den across warp
        float den = denl;
#pragma unroll
        for (int o = 16; o > 0; o >>= 1) den += __shfl_xor_sync(0xffffffffu, den, o);
        if (e > s) {
            float inv = 1.f / den;
            t0 = fmaf(acc0, inv, t0);
            t1 = fmaf(acc1, inv, t1);
        }
        t0 += __ldg(&bias[r * OUT_DIM + 2 * lane]);
        t1 += __ldg(&bias[r * OUT_DIM + 2 * lane + 1]);
    }
    t0 *= (1.f / 3.f);
    t1 *= (1.f / 3.f);
    if (LAYER == 1) {
        float sq = t0 * t0 + t1 * t1;
#pragma unroll
        for (int o = 16; o > 0; o >>= 1) sq += __shfl_xor_sync(0xffffffffu, sq, o);
        float inv = 1.f / fmaxf(sqrtf(sq), 1e-12f);
        t0 = fmaxf(t0 * inv, 0.f);
        t1 = fmaxf(t1 * inv, 0.f);
    }
    out[(size_t)d * (OUT_DIM / 2) + lane] = make_float2(t0, t1);
}

// ---------------- launch -----------------------------------------------------
extern "C" void kernel_launch(void* const* d_in, const int* in_sizes, int n_in,
                              void* d_out, int out_size) {
    const float* x      = (const float*)d_in[0];
    const int*   ei0    = (const int*)d_in[1];
    const int*   ei1    = (const int*)d_in[2];
    const int*   ei2    = (const int*)d_in[3];
    const float* W1     = (const float*)d_in[4];
    const float* asrc1  = (const float*)d_in[5];
    const float* adst1  = (const float*)d_in[6];
    const float* b1     = (const float*)d_in[7];
    const float* W2     = (const float*)d_in[8];
    const float* asrc2  = (const float*)d_in[9];
    const float* adst2  = (const float*)d_in[10];
    const float* b2     = (const float*)d_in[11];
    float2* out = (float2*)d_out;

    void* cntp;  cudaGetSymbolAddress(&cntp, g_cnt);
    float* hmid; cudaGetSymbolAddress((void**)&hmid, g_hmid);

    cudaMemsetAsync(cntp, 0, (size_t)N3 * sizeof(int));
    k_hist<<<(E3 + 255) / 256, 256>>>(ei0, ei1, ei2);
    k_scan_bsum<<<NB_SCAN, 256>>>();
    k_scan_off_par<<<1, 1024>>>();
    k_scan_final<<<NB_SCAN, 256>>>();
    k_scatter<<<(E3 + 255) / 256, 256>>>(ei0, ei1, ei2);

    dim3 ggrid((NN + 127) / 128, 1, RR);
    k_gemm_tc<IN_DIM><<<ggrid, 256>>>(x, W1, asrc1, adst1);
    k_agg<1><<<(NN * 32 + 255) / 256, 256>>>(b1, (float2*)hmid);

    k_gemm_tc<OUT_DIM><<<ggrid, 256>>>(hmid, W2, asrc2, adst2);
    k_agg<2><<<(NN * 32 + 255) / 256, 256>>>(b2, out);
}

// round 7
// speedup vs baseline: 1.0313x; 1.0313x over previous
#include <cuda_runtime.h>
#include <cuda_fp16.h>
#include <mma.h>
#include <math.h>

using namespace nvcuda;

#define NN 100000
#define EE 1000000
#define RR 3
#define IN_DIM 128
#define OUT_DIM 64

static constexpr int N3 = RR * NN;
static constexpr int E3 = RR * EE;
static constexpr int NB_SCAN = (N3 + 255) / 256;   // 1172

// ---------------- scratch ----------------------------------------------------
__device__ int     g_cnt[N3];
__device__ int     g_rowptr[N3 + 1];
__device__ int     g_col[E3];
__device__ unsigned long long g_lookback[NB_SCAN];
__device__ __half2 g_h2[(size_t)N3 * (OUT_DIM / 2)];
__device__ float   g_alsrc[N3];
__device__ float   g_aldst[N3];
__device__ float   g_hmid[(size_t)NN * OUT_DIM];

// ---------------- CSR build --------------------------------------------------
__global__ void k_hist(const int* __restrict__ e0, const int* __restrict__ e1,
                       const int* __restrict__ e2) {
    int i = blockIdx.x * blockDim.x + threadIdx.x;
    if (i >= E3) return;
    int r = i / EE, e = i - r * EE;
    const int* ei = (r == 0) ? e0 : (r == 1) ? e1 : e2;
    int dst = ei[EE + e];
    atomicAdd(&g_cnt[r * NN + dst], 1);
}

// single-pass decoupled-lookback exclusive scan of g_cnt -> g_rowptr (+cursor)
__global__ void k_scan_lookback() {
    __shared__ int sh[256];
    __shared__ int s_prefix;
    int b = blockIdx.x, tid = threadIdx.x;
    int i = b * 256 + tid;
    int v = (i < N3) ? g_cnt[i] : 0;
    sh[tid] = v;
    __syncthreads();
    for (int o = 1; o < 256; o <<= 1) {           // inclusive block scan
        int add = (tid >= o) ? sh[tid - o] : 0;
        __syncthreads();
        sh[tid] += add;
        __syncthreads();
    }
    int total = sh[255];
    if (tid == 0) {
        if (b == 0) {
            *(volatile unsigned long long*)&g_lookback[0] =
                (2ULL << 32) | (unsigned)total;
            s_prefix = 0;
        } else {
            *(volatile unsigned long long*)&g_lookback[b] =
                (1ULL << 32) | (unsigned)total;
            int run = 0, p = b - 1;
            while (true) {
                unsigned long long st = *(volatile unsigned long long*)&g_lookback[p];
                unsigned stt = (unsigned)(st >> 32);
                if (stt == 2u) { run += (int)(st & 0xffffffffu); break; }
                else if (stt == 1u) { run += (int)(st & 0xffffffffu); p--; }
                else { __nanosleep(20); }
            }
            *(volatile unsigned long long*)&g_lookback[b] =
                (2ULL << 32) | (unsigned)(run + total);
            s_prefix = run;
        }
    }
    __syncthreads();
    int excl = s_prefix + sh[tid] - v;
    if (i < N3) { g_rowptr[i] = excl; g_cnt[i] = excl; }
    if (i == 0) g_rowptr[N3] = E3;
}

__global__ void k_scatter(const int* __restrict__ e0, const int* __restrict__ e1,
                          const int* __restrict__ e2) {
    int i = blockIdx.x * blockDim.x + threadIdx.x;
    if (i >= E3) return;
    int r = i / EE, e = i - r * EE;
    const int* ei = (r == 0) ? e0 : (r == 1) ? e1 : e2;
    int src = ei[e];
    int dst = ei[EE + e];
    int pos = atomicAdd(&g_cnt[r * NN + dst], 1);
    g_col[pos] = src;
}

// ---------------- tensor-core GEMM (tf32): H[r] = X @ W[r], fused logits -----
template <int K>
__global__ __launch_bounds__(256) void k_gemm_tc(
        const float* __restrict__ X, const float* __restrict__ W,
        const float* __restrict__ asrc, const float* __restrict__ adst) {
    constexpr int XLD = 20;
    constexpr int OLD = 68;
    constexpr int BUF = ((K * 64 + 128 * XLD) > (128 * OLD)) ? (K * 64 + 128 * XLD)
                                                             : (128 * OLD);
    __shared__ float buf[BUF];
    float* sW = buf;
    float* sX = buf + K * 64;
    float* sO = buf;

    const int r = blockIdx.z;
    const int row0 = blockIdx.x * 128;
    const int t = threadIdx.x;
    const int w = t >> 5;

    {
        const float4* Wr4 = (const float4*)(W + (size_t)r * K * OUT_DIM);
        for (int i = t; i < K * 16; i += 256)
            *(float4*)&sW[i * 4] = Wr4[i];
    }

    wmma::fragment<wmma::accumulator, 16, 16, 8, float> acc[4];
#pragma unroll
    for (int ct = 0; ct < 4; ct++) wmma::fill_fragment(acc[ct], 0.f);

    for (int kk = 0; kk < K; kk += 16) {
#pragma unroll
        for (int p = 0; p < 2; p++) {
            int idx = t + p * 256;
            int row = idx >> 2, c4 = (idx & 3) * 4;
            int grow = row0 + row;
            float4 v = make_float4(0.f, 0.f, 0.f, 0.f);
            if (grow < NN) v = *(const float4*)(X + (size_t)grow * K + kk + c4);
            sX[row * XLD + c4 + 0] = v.x; sX[row * XLD + c4 + 1] = v.y;
            sX[row * XLD + c4 + 2] = v.z; sX[row * XLD + c4 + 3] = v.w;
        }
        __syncthreads();
#pragma unroll
        for (int kt = 0; kt < 2; kt++) {
            wmma::fragment<wmma::matrix_a, 16, 16, 8, wmma::precision::tf32, wmma::row_major> af;
            wmma::load_matrix_sync(af, &sX[(w * 16) * XLD + kt * 8], XLD);
#pragma unroll
            for (int i = 0; i < af.num_elements; i++)
                af.x[i] = wmma::__float_to_tf32(af.x[i]);
#pragma unroll
            for (int ct = 0; ct < 4; ct++) {
                wmma::fragment<wmma::matrix_b, 16, 16, 8, wmma::precision::tf32, wmma::row_major> bf;
                wmma::load_matrix_sync(bf, &sW[(kk + kt * 8) * 64 + ct * 16], 64);
#pragma unroll
                for (int i = 0; i < bf.num_elements; i++)
                    bf.x[i] = wmma::__float_to_tf32(bf.x[i]);
                wmma::mma_sync(acc[ct], af, bf, acc[ct]);
            }
        }
        __syncthreads();
    }

#pragma unroll
    for (int ct = 0; ct < 4; ct++)
        wmma::store_matrix_sync(&sO[(w * 16) * OLD + ct * 16], acc[ct], OLD, wmma::mem_row_major);
    __syncthreads();

    {
        int row = t >> 1, half = t & 1;
        int grow = row0 + row;
        float s = 0.f, d = 0.f;
        __half2 hv[16];
        const float* orow = &sO[row * OLD + half * 32];
        const float* av = asrc + r * OUT_DIM + half * 32;
        const float* dv = adst + r * OUT_DIM + half * 32;
#pragma unroll
        for (int j = 0; j < 16; j++) {
            float v0 = orow[2 * j], v1 = orow[2 * j + 1];
            hv[j] = __float22half2_rn(make_float2(v0, v1));
            s = fmaf(v0, __ldg(&av[2 * j]), s);
            s = fmaf(v1, __ldg(&av[2 * j + 1]), s);
            d = fmaf(v0, __ldg(&dv[2 * j]), d);
            d = fmaf(v1, __ldg(&dv[2 * j + 1]), d);
        }
        float so = __shfl_xor_sync(0xffffffffu, s, 1);
        float dof = __shfl_xor_sync(0xffffffffu, d, 1);
        s += so; d += dof;
        if (grow < NN) {
            float4* dstp = (float4*)(g_h2 + (size_t)(r * NN + grow) * 32 + half * 16);
            const float4* srcp = (const float4*)hv;
#pragma unroll
            for (int q = 0; q < 4; q++) dstp[q] = srcp[q];
            if (half == 0) {
                g_alsrc[r * NN + grow] = s;
                g_aldst[r * NN + grow] = d;
            }
        }
    }
}

// ---------------- aggregation (R5 serial form) -------------------------------
template <int LAYER>
__global__ void k_agg(const float* __restrict__ bias, float2* __restrict__ out) {
    int d = (blockIdx.x * blockDim.x + threadIdx.x) >> 5;
    int lane = threadIdx.x & 31;
    if (d >= NN) return;
    float t0 = 0.f, t1 = 0.f;
#pragma unroll
    for (int r = 0; r < RR; r++) {
        int idx = r * NN + d;
        int s = g_rowptr[idx], e = g_rowptr[idx + 1];
        float ad = g_aldst[idx];
        float acc0 = 0.f, acc1 = 0.f, den = 0.f;
        const __half2* hbase = g_h2 + (size_t)r * NN * (OUT_DIM / 2);
        const float* albase = g_alsrc + r * NN;
        for (int j = s; j < e; j++) {
            int src = g_col[j];
            float al = albase[src] + ad;
            float lr = al > 0.f ? al : 0.2f * al;
            float w = __expf(lr);
            den += w;
            float2 hv = __half22float2(hbase[(size_t)src * (OUT_DIM / 2) + lane]);
            acc0 = fmaf(w, hv.x, acc0);
            acc1 = fmaf(w, hv.y, acc1);
        }
        if (e > s) {
            float inv = 1.f / den;
            t0 = fmaf(acc0, inv, t0);
            t1 = fmaf(acc1, inv, t1);
        }
        t0 += __ldg(&bias[r * OUT_DIM + 2 * lane]);
        t1 += __ldg(&bias[r * OUT_DIM + 2 * lane + 1]);
    }
    t0 *= (1.f / 3.f);
    t1 *= (1.f / 3.f);
    if (LAYER == 1) {
        float sq = t0 * t0 + t1 * t1;
#pragma unroll
        for (int o = 16; o > 0; o >>= 1) sq += __shfl_xor_sync(0xffffffffu, sq, o);
        float inv = 1.f / fmaxf(sqrtf(sq), 1e-12f);
        t0 = fmaxf(t0 * inv, 0.f);
        t1 = fmaxf(t1 * inv, 0.f);
    }
    out[(size_t)d * (OUT_DIM / 2) + lane] = make_float2(t0, t1);
}

// ---------------- launch -----------------------------------------------------
extern "C" void kernel_launch(void* const* d_in, const int* in_sizes, int n_in,
                              void* d_out, int out_size) {
    const float* x      = (const float*)d_in[0];
    const int*   ei0    = (const int*)d_in[1];
    const int*   ei1    = (const int*)d_in[2];
    const int*   ei2    = (const int*)d_in[3];
    const float* W1     = (const float*)d_in[4];
    const float* asrc1  = (const float*)d_in[5];
    const float* adst1  = (const float*)d_in[6];
    const float* b1     = (const float*)d_in[7];
    const float* W2     = (const float*)d_in[8];
    const float* asrc2  = (const float*)d_in[9];
    const float* adst2  = (const float*)d_in[10];
    const float* b2     = (const float*)d_in[11];
    float2* out = (float2*)d_out;

    void* cntp;  cudaGetSymbolAddress(&cntp, g_cnt);
    void* lbp;   cudaGetSymbolAddress(&lbp, g_lookback);
    float* hmid; cudaGetSymbolAddress((void**)&hmid, g_hmid);

    cudaMemsetAsync(cntp, 0, (size_t)N3 * sizeof(int));
    cudaMemsetAsync(lbp, 0, (size_t)NB_SCAN * sizeof(unsigned long long));

    k_hist<<<(E3 + 255) / 256, 256>>>(ei0, ei1, ei2);           // launch 1
    k_scan_lookback<<<NB_SCAN, 256>>>();                         // launch 2
    k_scatter<<<(E3 + 255) / 256, 256>>>(ei0, ei1, ei2);        // launch 3

    dim3 ggrid((NN + 127) / 128, 1, RR);
    k_gemm_tc<IN_DIM><<<ggrid, 256>>>(x, W1, asrc1, adst1);     // launch 4 (captured)
    k_agg<1><<<(NN * 32 + 255) / 256, 256>>>(b1, (float2*)hmid);// launch 5

    k_gemm_tc<OUT_DIM><<<ggrid, 256>>>(hmid, W2, asrc2, adst2); // launch 6
    k_agg<2><<<(NN * 32 + 255) / 256, 256>>>(b2, out);          // launch 7
}

// round 8
// speedup vs baseline: 1.2647x; 1.2263x over previous
#include <cuda_runtime.h>
#include <cuda_fp16.h>
#include <mma.h>
#include <math.h>

using namespace nvcuda;

#define NN 100000
#define EE 1000000
#define RR 3
#define IN_DIM 128
#define OUT_DIM 64

static constexpr int N3 = RR * NN;
static constexpr int E3 = RR * EE;
static constexpr int NB_SCAN = (N3 + 255) / 256;   // 1172

// ---------------- scratch ----------------------------------------------------
__device__ int     g_cnt[N3];
__device__ int     g_rowptr[N3 + 1];
__device__ int     g_col[E3];
__device__ unsigned long long g_lookback[NB_SCAN];
__device__ __half2 g_h2[(size_t)N3 * (OUT_DIM / 2)];
__device__ float   g_alsrc[N3];
__device__ float   g_aldst[N3];
__device__ float   g_hmid[(size_t)NN * OUT_DIM];

// ---------------- CSR build --------------------------------------------------
__global__ void k_hist(const int* __restrict__ e0, const int* __restrict__ e1,
                       const int* __restrict__ e2) {
    int i = blockIdx.x * blockDim.x + threadIdx.x;
    if (i >= E3) return;
    int r = i / EE, e = i - r * EE;
    const int* ei = (r == 0) ? e0 : (r == 1) ? e1 : e2;
    int dst = ei[EE + e];
    atomicAdd(&g_cnt[r * NN + dst], 1);
}

__global__ void k_scan_lookback() {
    __shared__ int sh[256];
    __shared__ int s_prefix;
    int b = blockIdx.x, tid = threadIdx.x;
    int i = b * 256 + tid;
    int v = (i < N3) ? g_cnt[i] : 0;
    sh[tid] = v;
    __syncthreads();
    for (int o = 1; o < 256; o <<= 1) {
        int add = (tid >= o) ? sh[tid - o] : 0;
        __syncthreads();
        sh[tid] += add;
        __syncthreads();
    }
    int total = sh[255];
    if (tid == 0) {
        if (b == 0) {
            *(volatile unsigned long long*)&g_lookback[0] =
                (2ULL << 32) | (unsigned)total;
            s_prefix = 0;
        } else {
            *(volatile unsigned long long*)&g_lookback[b] =
                (1ULL << 32) | (unsigned)total;
            int run = 0, p = b - 1;
            while (true) {
                unsigned long long st = *(volatile unsigned long long*)&g_lookback[p];
                unsigned stt = (unsigned)(st >> 32);
                if (stt == 2u) { run += (int)(st & 0xffffffffu); break; }
                else if (stt == 1u) { run += (int)(st & 0xffffffffu); p--; }
                else { __nanosleep(20); }
            }
            *(volatile unsigned long long*)&g_lookback[b] =
                (2ULL << 32) | (unsigned)(run + total);
            s_prefix = run;
        }
    }
    __syncthreads();
    int excl = s_prefix + sh[tid] - v;
    if (i < N3) { g_rowptr[i] = excl; g_cnt[i] = excl; }
    if (i == 0) g_rowptr[N3] = E3;
}

__global__ void k_scatter(const int* __restrict__ e0, const int* __restrict__ e1,
                          const int* __restrict__ e2) {
    int i = blockIdx.x * blockDim.x + threadIdx.x;
    if (i >= E3) return;
    int r = i / EE, e = i - r * EE;
    const int* ei = (r == 0) ? e0 : (r == 1) ? e1 : e2;
    int src = ei[e];
    int dst = ei[EE + e];
    int pos = atomicAdd(&g_cnt[r * NN + dst], 1);
    g_col[pos] = src;
}

// ---------------- fp16 tensor-core GEMM: H[r] = X @ W[r], fused logits -------
// block: 256 threads (8 warps), tile 128 rows x 64 cols, m16n16k16 half wmma
template <int K>
__global__ __launch_bounds__(256) void k_gemm_tc(
        const float* __restrict__ X, const float* __restrict__ W,
        const float* __restrict__ asrc, const float* __restrict__ adst) {
    constexpr int XLDH = 24;                 // halves per X row (16 + 8 pad)
    constexpr int WLDH = 72;                 // halves per W row (64 + 8 pad)
    constexpr int OLD  = 68;                 // floats per O row
    constexpr int W_BYTES = K * WLDH * 2;
    constexpr int X_BYTES = 128 * XLDH * 2;
    constexpr int MAIN_BYTES = W_BYTES + X_BYTES;
    constexpr int O_BYTES = 128 * OLD * 4;
    constexpr int BUF_BYTES = (MAIN_BYTES > O_BYTES) ? MAIN_BYTES : O_BYTES;
    __shared__ __align__(16) char buf[BUF_BYTES];
    __half* sW = (__half*)buf;                       // [K][WLDH]
    __half* sX = (__half*)(buf + W_BYTES);           // [128][XLDH]
    float*  sO = (float*)buf;                        // epilogue stage (aliases)

    const int r = blockIdx.z;
    const int row0 = blockIdx.x * 128;
    const int t = threadIdx.x;
    const int w = t >> 5;

    // load whole W[r] into smem as half
    {
        const float4* Wr4 = (const float4*)(W + (size_t)r * K * OUT_DIM);
        for (int i = t; i < K * 16; i += 256) {      // float4 units
            float4 v = Wr4[i];
            int row = i >> 4, c4 = (i & 15) * 4;
            __half2* dstp = (__half2*)&sW[row * WLDH + c4];
            dstp[0] = __float22half2_rn(make_float2(v.x, v.y));
            dstp[1] = __float22half2_rn(make_float2(v.z, v.w));
        }
    }

    wmma::fragment<wmma::accumulator, 16, 16, 16, float> acc[4];
#pragma unroll
    for (int ct = 0; ct < 4; ct++) wmma::fill_fragment(acc[ct], 0.f);

    for (int kk = 0; kk < K; kk += 16) {
        // stage X tile [128 x 16] as half
#pragma unroll
        for (int p = 0; p < 2; p++) {
            int idx = t + p * 256;                   // 512 float4 loads
            int row = idx >> 2, c4 = (idx & 3) * 4;
            int grow = row0 + row;
            float4 v = make_float4(0.f, 0.f, 0.f, 0.f);
            if (grow < NN) v = *(const float4*)(X + (size_t)grow * K + kk + c4);
            __half2* dstp = (__half2*)&sX[row * XLDH + c4];
            dstp[0] = __float22half2_rn(make_float2(v.x, v.y));
            dstp[1] = __float22half2_rn(make_float2(v.z, v.w));
        }
        __syncthreads();
        wmma::fragment<wmma::matrix_a, 16, 16, 16, __half, wmma::row_major> af;
        wmma::load_matrix_sync(af, &sX[(w * 16) * XLDH], XLDH);
#pragma unroll
        for (int ct = 0; ct < 4; ct++) {
            wmma::fragment<wmma::matrix_b, 16, 16, 16, __half, wmma::row_major> bf;
            wmma::load_matrix_sync(bf, &sW[kk * WLDH + ct * 16], WLDH);
            wmma::mma_sync(acc[ct], af, bf, acc[ct]);
        }
        __syncthreads();
    }

    // stage accumulators to smem (aliases mainloop buffers; dead now)
#pragma unroll
    for (int ct = 0; ct < 4; ct++)
        wmma::store_matrix_sync(&sO[(w * 16) * OLD + ct * 16], acc[ct], OLD, wmma::mem_row_major);
    __syncthreads();

    // epilogue: 2 threads per row, 32 cols each -> fp16 store + logits
    {
        int row = t >> 1, half = t & 1;
        int grow = row0 + row;
        float s = 0.f, d = 0.f;
        __half2 hv[16];
        const float* orow = &sO[row * OLD + half * 32];
        const float* av = asrc + r * OUT_DIM + half * 32;
        const float* dv = adst + r * OUT_DIM + half * 32;
#pragma unroll
        for (int j = 0; j < 16; j++) {
            float v0 = orow[2 * j], v1 = orow[2 * j + 1];
            hv[j] = __float22half2_rn(make_float2(v0, v1));
            s = fmaf(v0, __ldg(&av[2 * j]), s);
            s = fmaf(v1, __ldg(&av[2 * j + 1]), s);
            d = fmaf(v0, __ldg(&dv[2 * j]), d);
            d = fmaf(v1, __ldg(&dv[2 * j + 1]), d);
        }
        float so = __shfl_xor_sync(0xffffffffu, s, 1);
        float dof = __shfl_xor_sync(0xffffffffu, d, 1);
        s += so; d += dof;
        if (grow < NN) {
            float4* dstp = (float4*)(g_h2 + (size_t)(r * NN + grow) * 32 + half * 16);
            const float4* srcp = (const float4*)hv;
#pragma unroll
            for (int q = 0; q < 4; q++) dstp[q] = srcp[q];
            if (half == 0) {
                g_alsrc[r * NN + grow] = s;
                g_aldst[r * NN + grow] = d;
            }
        }
    }
}

// ---------------- aggregation ------------------------------------------------
template <int LAYER>
__global__ void k_agg(const float* __restrict__ bias, float2* __restrict__ out) {
    int d = (blockIdx.x * blockDim.x + threadIdx.x) >> 5;
    int lane = threadIdx.x & 31;
    if (d >= NN) return;
    float t0 = 0.f, t1 = 0.f;
#pragma unroll
    for (int r = 0; r < RR; r++) {
        int idx = r * NN + d;
        int s = g_rowptr[idx], e = g_rowptr[idx + 1];
        float ad = g_aldst[idx];
        float acc0 = 0.f, acc1 = 0.f, den = 0.f;
        const __half2* hbase = g_h2 + (size_t)r * NN * (OUT_DIM / 2);
        const float* albase = g_alsrc + r * NN;
        for (int j = s; j < e; j++) {
            int src = g_col[j];
            float al = albase[src] + ad;
            float lr = al > 0.f ? al : 0.2f * al;
            float w = __expf(lr);
            den += w;
            float2 hv = __half22float2(hbase[(size_t)src * (OUT_DIM / 2) + lane]);
            acc0 = fmaf(w, hv.x, acc0);
            acc1 = fmaf(w, hv.y, acc1);
        }
        if (e > s) {
            float inv = 1.f / den;
            t0 = fmaf(acc0, inv, t0);
            t1 = fmaf(acc1, inv, t1);
        }
        t0 += __ldg(&bias[r * OUT_DIM + 2 * lane]);
        t1 += __ldg(&bias[r * OUT_DIM + 2 * lane + 1]);
    }
    t0 *= (1.f / 3.f);
    t1 *= (1.f / 3.f);
    if (LAYER == 1) {
        float sq = t0 * t0 + t1 * t1;
#pragma unroll
        for (int o = 16; o > 0; o >>= 1) sq += __shfl_xor_sync(0xffffffffu, sq, o);
        float inv = 1.f / fmaxf(sqrtf(sq), 1e-12f);
        t0 = fmaxf(t0 * inv, 0.f);
        t1 = fmaxf(t1 * inv, 0.f);
    }
    out[(size_t)d * (OUT_DIM / 2) + lane] = make_float2(t0, t1);
}

// ---------------- launch -----------------------------------------------------
extern "C" void kernel_launch(void* const* d_in, const int* in_sizes, int n_in,
                              void* d_out, int out_size) {
    const float* x      = (const float*)d_in[0];
    const int*   ei0    = (const int*)d_in[1];
    const int*   ei1    = (const int*)d_in[2];
    const int*   ei2    = (const int*)d_in[3];
    const float* W1     = (const float*)d_in[4];
    const float* asrc1  = (const float*)d_in[5];
    const float* adst1  = (const float*)d_in[6];
    const float* b1     = (const float*)d_in[7];
    const float* W2     = (const float*)d_in[8];
    const float* asrc2  = (const float*)d_in[9];
    const float* adst2  = (const float*)d_in[10];
    const float* b2     = (const float*)d_in[11];
    float2* out = (float2*)d_out;

    void* cntp;  cudaGetSymbolAddress(&cntp, g_cnt);
    void* lbp;   cudaGetSymbolAddress(&lbp, g_lookback);
    float* hmid; cudaGetSymbolAddress((void**)&hmid, g_hmid);

    cudaMemsetAsync(cntp, 0, (size_t)N3 * sizeof(int));
    cudaMemsetAsync(lbp, 0, (size_t)NB_SCAN * sizeof(unsigned long long));

    k_hist<<<(E3 + 255) / 256, 256>>>(ei0, ei1, ei2);           // launch 1
    k_scan_lookback<<<NB_SCAN, 256>>>();                         // launch 2
    k_scatter<<<(E3 + 255) / 256, 256>>>(ei0, ei1, ei2);        // launch 3

    dim3 ggrid((NN + 127) / 128, 1, RR);
    k_gemm_tc<IN_DIM><<<ggrid, 256>>>(x, W1, asrc1, adst1);     // launch 4 (captured)
    k_agg<1><<<(NN * 32 + 255) / 256, 256>>>(b1, (float2*)hmid);// launch 5

    k_gemm_tc<OUT_DIM><<<ggrid, 256>>>(hmid, W2, asrc2, adst2); // launch 6
    k_agg<2><<<(NN * 32 + 255) / 256, 256>>>(b2, out);          // launch 7
}